// round 7
// baseline (speedup 1.0000x reference)
#include <cuda_runtime.h>
#include <cuda_bf16.h>
#include <cstdint>

// ---------------------------------------------------------------------------
// Problem constants
// ---------------------------------------------------------------------------
#define D_IN   992
#define HID    32
#define NKS    62            // 992 / 16 k-steps
#define KSPLIT 31            // k-steps per warp (2-way split)
#define TMROWS 128           // rows per CTA

// W in mma B-fragment layout (k-permuted), bf16 hi/lo packed per lane:
// [ks 62][nt 4][lane 32] -> uint4 (bh0, bh1, bl0, bl1)
__device__ uint4 g_Wf[NKS * 4 * 32];

// ---------------------------------------------------------------------------
// smem layout (floats) — dynamic
// ---------------------------------------------------------------------------
#define SM_AB   0                         // 8 warps * 3 stages * 512 = 12288
#define SM_HS   12288                     // 128*33 = 4224
#define SM_PP   16512                     // 128*33 = 4224
#define SM_CW0  20736                     // 32*12*6 = 2304
#define SM_WB0  23040                     // 192
#define SM_CW1  23232                     // 72
#define SM_WB1  23304                     // 6
#define SM_B0   23310                     // 6
#define SM_B1   23316                     // 1
#define SM_TOTF 23320
#define SM_BYTES (SM_TOTF * 4)            // 93280

// ---------------------------------------------------------------------------
// helpers
// ---------------------------------------------------------------------------
__device__ __forceinline__ uint32_t smem_u32(const void* p) {
    uint32_t a;
    asm("{ .reg .u64 t; cvta.to.shared.u64 t, %1; cvt.u32.u64 %0, t; }"
        : "=r"(a) : "l"(p));
    return a;
}
__device__ __forceinline__ uint32_t packbf(float e0, float e1) {
    uint32_t r;
    asm("cvt.rn.bf16x2.f32 %0, %1, %2;" : "=r"(r) : "f"(e1), "f"(e0));
    return r;
}
__device__ __forceinline__ void unpackbf(uint32_t p, float& e0, float& e1) {
    e0 = __uint_as_float(p << 16);
    e1 = __uint_as_float(p & 0xFFFF0000u);
}
__device__ __forceinline__ void mma_bf16(float d[4], uint32_t a0, uint32_t a1,
                                         uint32_t a2, uint32_t a3,
                                         uint32_t b0, uint32_t b1) {
    asm volatile(
        "mma.sync.aligned.m16n8k16.row.col.f32.bf16.bf16.f32 "
        "{%0,%1,%2,%3}, {%4,%5,%6,%7}, {%8,%9}, {%0,%1,%2,%3};"
        : "+f"(d[0]), "+f"(d[1]), "+f"(d[2]), "+f"(d[3])
        : "r"(a0), "r"(a1), "r"(a2), "r"(a3), "r"(b0), "r"(b1));
}
__device__ __forceinline__ void cp_async16(uint32_t dst, const float* src) {
    asm volatile("cp.async.cg.shared.global [%0], [%1], 16;"
                 :: "r"(dst), "l"(src) : "memory");
}
#define CP_COMMIT() asm volatile("cp.async.commit_group;" ::: "memory")
#define CP_WAIT1()  asm volatile("cp.async.wait_group 1;" ::: "memory")

// f32x2 packed helpers (KAN phase)
__device__ __forceinline__ uint64_t f2dup(float x) {
    uint64_t r; asm("mov.b64 %0, {%1, %1};" : "=l"(r) : "f"(x)); return r;
}
__device__ __forceinline__ void f2unpack(uint64_t v, float& x, float& y) {
    asm("mov.b64 {%0, %1}, %2;" : "=f"(x), "=f"(y) : "l"(v));
}
__device__ __forceinline__ void ffma2(uint64_t& d, uint64_t a, uint64_t b) {
    asm("fma.rn.f32x2 %0, %1, %2, %0;" : "+l"(d) : "l"(a), "l"(b));
}

// degree-4 uniform B-spline basis (5 nonzero values), matches reference
__device__ __forceinline__ void bspline4(float u, float bw[5]) {
    const float um = 1.f - u;
    float c0 = um, c1 = u;
    float d0 = 0.5f * (um * c0);
    float d1 = 0.5f * ((u + 1.f) * c0 + (2.f - u) * c1);
    float d2 = 0.5f * (u * c1);
    const float i3 = 1.f / 3.f;
    float e0 = i3 * (um * d0);
    float e1 = i3 * ((u + 2.f) * d0 + (2.f - u) * d1);
    float e2 = i3 * ((u + 1.f) * d1 + (3.f - u) * d2);
    float e3 = i3 * (u * d2);
    bw[0] = 0.25f * (um * e0);
    bw[1] = 0.25f * ((u + 3.f) * e0 + (2.f - u) * e1);
    bw[2] = 0.25f * ((u + 2.f) * e1 + (3.f - u) * e2);
    bw[3] = 0.25f * ((u + 1.f) * e2 + (4.f - u) * e3);
    bw[4] = 0.25f * (u * e3);
}
__device__ __forceinline__ float silu_f(float x) { return x / (1.f + __expf(-x)); }

// ---------------------------------------------------------------------------
// W pre-conversion with k-permutation (unchanged):
// lane (g,t4), nt: b0 = {W[ks16+4t4][n], W[ks16+4t4+1][n]},
//                  b1 = {W[ks16+4t4+2][n], W[ks16+4t4+3][n]}, n = nt*8+g
// ---------------------------------------------------------------------------
__global__ void wfrag_kernel(const float* __restrict__ W) {
    int idx = blockIdx.x * 256 + threadIdx.x;     // 62*4*32 = 7936
    if (idx >= NKS * 4 * 32) return;
    int lane = idx & 31;
    int nt   = (idx >> 5) & 3;
    int ks   = idx >> 7;
    int g = lane >> 2, t4 = lane & 3;
    int n  = nt * 8 + g;
    int ka = ks * 16 + t4 * 4;

    float x0 = W[(ka + 0) * HID + n];
    float x1 = W[(ka + 1) * HID + n];
    float y0 = W[(ka + 2) * HID + n];
    float y1 = W[(ka + 3) * HID + n];

    uint32_t h0 = packbf(x0, x1), h1 = packbf(y0, y1);
    float e0, e1;
    unpackbf(h0, e0, e1);
    uint32_t l0 = packbf(x0 - e0, x1 - e1);
    unpackbf(h1, e0, e1);
    uint32_t l1 = packbf(y0 - e0, y1 - e1);

    g_Wf[idx] = make_uint4(h0, h1, l0, l1);
}

// ---------------------------------------------------------------------------
// Fused kernel: warp-autonomous cp.async A pipeline (3-stage, per-warp smem,
// no CTA barriers in mainloop) + k-split warp pairs + W register prefetch.
//   warp w (w<4)  : m-tiles 2w, 2w+1 (rows w*32..w*32+31), k-steps 0..30
//   warp w+4      : same m-tiles,                          k-steps 31..61
// ---------------------------------------------------------------------------
__global__ void __launch_bounds__(256, 2)
fused_kernel(const float* __restrict__ A, const float* __restrict__ bias,
             const float* __restrict__ coef0, const float* __restrict__ wb0,
             const float* __restrict__ ws0,   const float* __restrict__ b0,
             const float* __restrict__ coef1, const float* __restrict__ wb1,
             const float* __restrict__ ws1,   const float* __restrict__ b1,
             float* __restrict__ out, int N)
{
    extern __shared__ __align__(16) float smem[];
    float* Abuf = smem + SM_AB;
    float* hs   = smem + SM_HS;
    float* pp   = smem + SM_PP;
    float* cw0s = smem + SM_CW0;
    float* wb0s = smem + SM_WB0;
    float* cw1s = smem + SM_CW1;
    float* wb1s = smem + SM_WB1;
    float* b0s  = smem + SM_B0;
    float* b1s  = smem + SM_B1;

    const int tid  = threadIdx.x;
    const int warp = tid >> 5;
    const int lane = tid & 31;
    const int g    = lane >> 2;
    const int t4   = lane & 3;
    const int wp   = warp & 3;        // m-pair id (rows wp*32..wp*32+31)
    const int kh   = warp >> 2;       // k-half (0: steps 0..30, 1: 31..61)
    const int off  = kh * KSPLIT;
    const int row0 = blockIdx.x * TMROWS;

    // ---- stage KAN tables ----
    for (int idx = tid; idx < 32 * 12 * 6; idx += 256) {
        int i = idx / 72, rem = idx % 72, j = rem / 6, o = rem % 6;
        cw0s[idx] = coef0[(i * 6 + o) * 12 + j] * ws0[i * 6 + o];
    }
    if (tid < 32 * 6) wb0s[tid] = wb0[tid];
    if (tid < 72) cw1s[tid] = coef1[tid] * ws1[tid / 12];
    if (tid < 6)  { wb1s[tid] = wb1[tid]; b0s[tid] = b0[tid]; }
    if (tid == 0) b1s[0] = b1[0];

    // ---- cp.async loader mapping: lane covers 4 rows (it*8 + lane>>2),
    //      16B segment (lane&3) of each row's 64B k-chunk ----
    const int rsub = lane >> 2;
    const int seg  = lane & 3;
    const float* gp[4];
    #pragma unroll
    for (int it = 0; it < 4; it++) {
        int rl = it * 8 + rsub;                  // local row 0..31
        int mt = rl >> 4, r16 = rl & 15;
        int grow = row0 + (wp * 2 + mt) * 16 + r16;
        if (grow > N - 1) grow = N - 1;
        gp[it] = A + (size_t)grow * D_IN + seg * 4;
    }

    // per-warp ring: 3 stages x 512 floats
    float* wbuf = Abuf + warp * (3 * 512);
    const uint32_t wb_addr = smem_u32(wbuf);

    // issue stage (s mod 3) for k-step ks
    auto issue = [&](int s, int ks) {
        uint32_t base = wb_addr + (uint32_t)(s % 3) * 2048u
                      + (uint32_t)(rsub * 64 + seg * 16);
        const int go = ks * 16;
        #pragma unroll
        for (int it = 0; it < 4; it++)
            cp_async16(base + it * 512u, gp[it] + go);
        CP_COMMIT();
    };

    issue(0, off);
    issue(1, off + 1);

    // W prefetch (depth 1)
    uint4 wv[4];
    {
        const uint4* wq = &g_Wf[(size_t)(off * 4) * 32 + lane];
        #pragma unroll
        for (int nt = 0; nt < 4; nt++) wv[nt] = wq[nt * 32];
    }

    float acc[2][4][4];
    #pragma unroll
    for (int mt = 0; mt < 2; mt++)
        #pragma unroll
        for (int nt = 0; nt < 4; nt++)
            #pragma unroll
            for (int r = 0; r < 4; r++) acc[mt][nt][r] = 0.f;

    // ---- mainloop: 31 k-steps, warp-autonomous, no CTA barriers ----
    for (int s = 0; s < KSPLIT; s++) {
        CP_WAIT1();                       // stage s landed (per-warp)

        uint4 w[4];
        #pragma unroll
        for (int nt = 0; nt < 4; nt++) w[nt] = wv[nt];
        if (s + 1 < KSPLIT) {
            const uint4* wq = &g_Wf[(size_t)((off + s + 1) * 4) * 32 + lane];
            #pragma unroll
            for (int nt = 0; nt < 4; nt++) wv[nt] = wq[nt * 32];
        }

        if (s + 2 < KSPLIT) issue(s + 2, off + s + 2);
        else CP_COMMIT();                 // keep pending-group invariant

        const float* buf = wbuf + (s % 3) * 512;
        #pragma unroll
        for (int mt = 0; mt < 2; mt++) {
            float4 av0 = *(const float4*)&buf[(mt * 16 + g) * 16 + t4 * 4];
            float4 av1 = *(const float4*)&buf[(mt * 16 + 8 + g) * 16 + t4 * 4];

            uint32_t ah0 = packbf(av0.x, av0.y);
            uint32_t ah1 = packbf(av1.x, av1.y);
            uint32_t ah2 = packbf(av0.z, av0.w);
            uint32_t ah3 = packbf(av1.z, av1.w);

            float e0, e1;
            uint32_t al0, al1, al2, al3;
            unpackbf(ah0, e0, e1); al0 = packbf(av0.x - e0, av0.y - e1);
            unpackbf(ah1, e0, e1); al1 = packbf(av1.x - e0, av1.y - e1);
            unpackbf(ah2, e0, e1); al2 = packbf(av0.z - e0, av0.w - e1);
            unpackbf(ah3, e0, e1); al3 = packbf(av1.z - e0, av1.w - e1);

            #pragma unroll
            for (int nt = 0; nt < 4; nt++) {
                mma_bf16(acc[mt][nt], ah0, ah1, ah2, ah3, w[nt].x, w[nt].y);
                mma_bf16(acc[mt][nt], ah0, ah1, ah2, ah3, w[nt].z, w[nt].w);
                mma_bf16(acc[mt][nt], al0, al1, al2, al3, w[nt].x, w[nt].y);
            }
        }
    }

    // ---- combine halves: upper dumps partials, lower adds + bias + transpose
    if (kh == 1) {
        #pragma unroll
        for (int nt = 0; nt < 4; nt++)
            #pragma unroll
            for (int mt = 0; mt < 2; mt++) {
                int rl = (wp * 2 + mt) * 16 + g;
                int c0 = nt * 8 + t4 * 2;
                pp[rl * 33 + c0]           = acc[mt][nt][0];
                pp[rl * 33 + c0 + 1]       = acc[mt][nt][1];
                pp[(rl + 8) * 33 + c0]     = acc[mt][nt][2];
                pp[(rl + 8) * 33 + c0 + 1] = acc[mt][nt][3];
            }
    }
    __syncthreads();
    if (kh == 0) {
        #pragma unroll
        for (int nt = 0; nt < 4; nt++) {
            float2 bv = *(const float2*)&bias[nt * 8 + t4 * 2];
            #pragma unroll
            for (int mt = 0; mt < 2; mt++) {
                int rl = (wp * 2 + mt) * 16 + g;
                int c0 = nt * 8 + t4 * 2;
                hs[rl * 33 + c0]           = acc[mt][nt][0] + pp[rl * 33 + c0]           + bv.x;
                hs[rl * 33 + c0 + 1]       = acc[mt][nt][1] + pp[rl * 33 + c0 + 1]       + bv.y;
                hs[(rl + 8) * 33 + c0]     = acc[mt][nt][2] + pp[(rl + 8) * 33 + c0]     + bv.x;
                hs[(rl + 8) * 33 + c0 + 1] = acc[mt][nt][3] + pp[(rl + 8) * 33 + c0 + 1] + bv.y;
            }
        }
    }
    __syncthreads();

    // ---- KAN layer 0: 2 threads per row, each handles 16 of 32 inputs ----
    const int r = tid & 127;          // row within CTA
    const int h = tid >> 7;           // half (0: i 0..15, 1: i 16..31)

    uint64_t kacc[3];
    kacc[0] = kacc[1] = kacc[2] = 0ull;

    #pragma unroll
    for (int i2 = 0; i2 < 16; i2++) {
        const int i = h * 16 + i2;
        float x  = hs[r * 33 + i];
        float sg = silu_f(x);
        uint64_t sgd = f2dup(sg);
        const uint64_t* wbp = (const uint64_t*)&wb0s[i * 6];
        ffma2(kacc[0], sgd, wbp[0]);
        ffma2(kacc[1], sgd, wbp[1]);
        ffma2(kacc[2], sgd, wbp[2]);

        float t = (x + 2.f) * 4.f;
        if (t >= 0.f && t < 16.f) {
            float cf = floorf(t);
            int   c  = (int)cf;
            float u  = t - cf;
            float bw[5];
            bspline4(u, bw);
            #pragma unroll
            for (int k = 0; k < 5; k++) {
                int j = c - 4 + k;
                if (j >= 0 && j < 12) {
                    uint64_t bd = f2dup(bw[k]);
                    const uint64_t* cp = (const uint64_t*)&cw0s[i * 72 + j * 6];
                    ffma2(kacc[0], bd, cp[0]);
                    ffma2(kacc[1], bd, cp[1]);
                    ffma2(kacc[2], bd, cp[2]);
                }
            }
        }
    }
    __syncthreads();                     // pp free for reuse as partial buffer
    {
        float p0, p1, p2, p3, p4, p5;
        f2unpack(kacc[0], p0, p1);
        f2unpack(kacc[1], p2, p3);
        f2unpack(kacc[2], p4, p5);
        float* q = &pp[r * 12 + h * 6];
        q[0] = p0; q[1] = p1; q[2] = p2;
        q[3] = p3; q[4] = p4; q[5] = p5;
    }
    __syncthreads();

    // ---- KAN layer 1 (half 0 threads only) ----
    if (h == 0) {
        const int row = row0 + r;
        if (row < N) {
            float res = b1s[0];
            #pragma unroll
            for (int i = 0; i < 6; i++) {
                float x = pp[r * 12 + i] + pp[r * 12 + 6 + i] + b0s[i];
                res += silu_f(x) * wb1s[i];
                float t = (x + 2.f) * 4.f;
                if (t >= 0.f && t < 16.f) {
                    float cf = floorf(t);
                    int   c  = (int)cf;
                    float u  = t - cf;
                    float bw[5];
                    bspline4(u, bw);
                    #pragma unroll
                    for (int k = 0; k < 5; k++) {
                        int j = c - 4 + k;
                        if (j >= 0 && j < 12) res += bw[k] * cw1s[i * 12 + j];
                    }
                }
            }
            out[row] = res;
        }
    }
}

// ---------------------------------------------------------------------------
// Launch
// ---------------------------------------------------------------------------
extern "C" void kernel_launch(void* const* d_in, const int* in_sizes, int n_in,
                              void* d_out, int out_size)
{
    const float* node_rep = (const float*)d_in[0];
    const float* mlp_w    = (const float*)d_in[1];
    const float* mlp_b    = (const float*)d_in[2];
    const float* coef0    = (const float*)d_in[3];
    const float* wb0      = (const float*)d_in[4];
    const float* ws0      = (const float*)d_in[5];
    const float* b0       = (const float*)d_in[6];
    const float* coef1    = (const float*)d_in[7];
    const float* wb1      = (const float*)d_in[8];
    const float* ws1      = (const float*)d_in[9];
    const float* b1       = (const float*)d_in[10];

    int N = in_sizes[0] / D_IN;

    cudaFuncSetAttribute(fused_kernel,
                         cudaFuncAttributeMaxDynamicSharedMemorySize, SM_BYTES);

    wfrag_kernel<<<(NKS * 4 * 32 + 255) / 256, 256>>>(mlp_w);
    fused_kernel<<<(N + TMROWS - 1) / TMROWS, 256, SM_BYTES>>>(
        node_rep, mlp_b, coef0, wb0, ws0, b0, coef1, wb1, ws1, b1,
        (float*)d_out, N);
}